// round 13
// baseline (speedup 1.0000x reference)
#include <cuda_runtime.h>
#include <cstdint>

#define BB 32
#define TT 128
#define DD 512
#define UU 512
#define G4 2048
#define NCTA 128
#define NTHR 512

// ---------------- scratch (device globals: allocation-free) ----------------
__device__ float g_attx[BB*TT*UU];      // 8 MB   tanh(x@W_att + b_att)
__device__ float g_xk  [BB*TT*G4];      // 32 MB  x@kernel + bias
__device__ float g_hbuf[BB*UU];         // hidden state
__device__ float g_hU  [BB*UU];         // tanh(h @ Ua), assembled per step
__device__ float g_hUp [NCTA*BB*UU];    // per-CTA rank-4 partials of h@Ua (8MB)
__device__ float g_z   [BB*DD];
__device__ float g_sc  [BB*TT];
__device__ unsigned g_gcnt, g_ggen;          // grid barrier
__device__ unsigned g_lcnt[BB], g_lgen[BB];  // per-batch 4-CTA barriers

__device__ __forceinline__ float my_tanh(float x) {
    x = fminf(fmaxf(x, -15.f), 15.f);
    float e = __expf(2.f * x);
    return __fdividef(e - 1.f, e + 1.f);
}
__device__ __forceinline__ float hsig(float x) {
    return fminf(fmaxf(0.2f * x + 0.5f, 0.f), 1.f);
}

// Software barrier. Safe: all participating CTAs co-resident (1 CTA/SM,
// 128 <= 148 SMs). __threadfence publishes prior writes and invalidates L1.
__device__ __forceinline__ void bar_sync(unsigned* cnt, unsigned* gen, unsigned n) {
    __syncthreads();
    if (threadIdx.x == 0) {
        __threadfence();
        unsigned my = *(volatile unsigned*)gen;
        if (atomicAdd(cnt, 1u) == n - 1u) {
            *cnt = 0u;
            __threadfence();
            atomicAdd(gen, 1u);
        } else {
            while (*(volatile unsigned*)gen == my) { }
        }
        __threadfence();
    }
    __syncthreads();
}

__device__ __forceinline__ void cp_async16(uint32_t dst_smem, const void* src) {
    asm volatile("cp.async.ca.shared.global [%0], [%1], 16;\n"
                 :: "r"(dst_smem), "l"(src));
}

// ---------------- precompute: one SGEMM over virtual N = 2048 + 512 --------
// n<2048 -> g_xk = X@kernel + bias ; n>=2048 -> g_attx = tanh(X@W_att + ab)
__global__ void __launch_bounds__(256) k_pre(
        const float* __restrict__ x, const float* __restrict__ Wk,
        const float* __restrict__ Wa, const float* __restrict__ bias,
        const float* __restrict__ ab) {
    __shared__ float As[16][132];
    __shared__ float Bs[16][64];
    int m0 = blockIdx.y * 128;
    int n0 = blockIdx.x * 64;
    bool isK = (n0 < G4);
    const float* Wm = isK ? Wk : Wa;
    int ldw = isK ? G4 : UU;
    int nc0 = isK ? n0 : (n0 - G4);
    int tid = threadIdx.x;
    int tm = (tid >> 4) * 8;
    int tn = (tid & 15) * 4;
    float acc[8][4];
    #pragma unroll
    for (int i = 0; i < 8; i++)
        #pragma unroll
        for (int j = 0; j < 4; j++) acc[i][j] = 0.f;

    for (int k0 = 0; k0 < DD; k0 += 16) {
        #pragma unroll
        for (int i = 0; i < 2; i++) {
            int idx = tid + i * 256;
            int row = idx >> 2;
            int c4  = (idx & 3) * 4;
            float4 v = *(const float4*)(x + (size_t)(m0 + row) * DD + k0 + c4);
            As[c4+0][row] = v.x; As[c4+1][row] = v.y;
            As[c4+2][row] = v.z; As[c4+3][row] = v.w;
        }
        {
            int row = tid >> 4;
            int c4  = (tid & 15) * 4;
            *(float4*)&Bs[row][c4] =
                *(const float4*)(Wm + (size_t)(k0 + row) * ldw + nc0 + c4);
        }
        __syncthreads();
        #pragma unroll
        for (int kk = 0; kk < 16; kk++) {
            float4 a0 = *(float4*)&As[kk][tm];
            float4 a1 = *(float4*)&As[kk][tm + 4];
            float4 bv = *(float4*)&Bs[kk][tn];
            float am[8] = {a0.x,a0.y,a0.z,a0.w,a1.x,a1.y,a1.z,a1.w};
            float bn[4] = {bv.x,bv.y,bv.z,bv.w};
            #pragma unroll
            for (int i = 0; i < 8; i++)
                #pragma unroll
                for (int j = 0; j < 4; j++)
                    acc[i][j] = fmaf(am[i], bn[j], acc[i][j]);
        }
        __syncthreads();
    }
    const float* bvec = isK ? bias : ab;
    float bj[4];
    #pragma unroll
    for (int j = 0; j < 4; j++) bj[j] = bvec[nc0 + tn + j];
    #pragma unroll
    for (int i = 0; i < 8; i++) {
        int m = m0 + tm + i;
        if (isK) {
            float* dst = g_xk + (size_t)m * G4 + nc0 + tn;
            #pragma unroll
            for (int j = 0; j < 4; j++) dst[j] = acc[i][j] + bj[j];
        } else {
            float* dst = g_attx + (size_t)m * UU + nc0 + tn;
            #pragma unroll
            for (int j = 0; j < 4; j++) dst[j] = my_tanh(acc[i][j] + bj[j]);
        }
    }
}

// ---------------- persistent scan kernel ------------------------------------
// 128 CTAs x 512 thr, 1 CTA/SM, ~219 KB smem.
// Phase A (CTA=(pb,pr)): cp.async prefetch h into hz; assemble hU slice from
//   partials (tanh) -> lbar -> scores (tanh addition formula) -> lbar ->
//   softmax + z.                                                 [grid bar]
// Phase B (CTA=u-tile): stage z; gates = xk + [h;z]@[R;A]; LSTM pointwise
//   (c in smem); rank-4 hU partial h_new_tile @ Ua[u0:u0+4,:].   [grid bar]
// smem: W_s[16384] Ua2_s[2048] hz[32768] gate_s[512] hnew_s[128] c_s[128]
//       Asc[4096]
__global__ void __launch_bounds__(NTHR, 1) k_scan(
        const float* __restrict__ x,  const float* __restrict__ R,
        const float* __restrict__ A,  const float* __restrict__ Ua,
        const float* __restrict__ V,  float* __restrict__ out) {
    extern __shared__ float sm[];
    float* W_s    = sm;               // 16384
    float* Ua2_s  = sm + 16384;       // 2048
    float* hz     = sm + 18432;       // 32768 (dedicated, never aliased)
    float* gate_s = sm + 51200;       // 512
    float* hnew_s = sm + 51712;       // 128
    float* c_s    = sm + 51840;       // 128
    float* Asc    = sm + 51968;       // 4096 (Phase-A scratch / Phase-B red)
    float* V_s    = sm + 56064;       // 512
    // total 56576 floats = 226304 B

    float2* pair_s = (float2*)Asc;            // 512
    float*  al_s   = Asc + 1024;              // 128
    float4* zred4  = (float4*)(Asc + 1152);   // 512 float4
    float*  wr     = Asc + 3200;              // 8
    float*  sred   = Asc + 3208;              // 512

    const int bid = blockIdx.x;
    const int tid = threadIdx.x;
    const int u0  = bid * 4;                  // Phase B u-tile
    const int wid = tid >> 5, lane = tid & 31;
    const int pb  = bid >> 2, pr = bid & 3;   // Phase A role
    const uint32_t hz_u32 = (uint32_t)__cvta_generic_to_shared(hz);

    // ---- one-time init ----
    if (tid < 128) {
        g_hbuf[bid * 128 + tid] = 0.f;
        c_s[tid] = 0.f;
    }
    {   // zero my hU partial (4096 float4)
        float4 zz = make_float4(0.f, 0.f, 0.f, 0.f);
        float4* p = (float4*)(g_hUp + (size_t)bid * BB * UU);
        #pragma unroll
        for (int i = 0; i < 8; i++) p[tid + i * 512] = zz;
    }
    #pragma unroll 4
    for (int i = 0; i < 32; i++) {            // gate weights [R;A]
        int idx = tid + i * 512;
        int k = idx >> 4, ci = idx & 15;
        int col = ((ci >> 2) << 9) + u0 + (ci & 3);
        W_s[idx] = (k < 512) ? R[(size_t)k * G4 + col]
                             : A[(size_t)(k - 512) * G4 + col];
    }
    #pragma unroll
    for (int i = 0; i < 4; i++) {             // Ua rows u0..u0+3
        int idx = tid + i * 512;
        Ua2_s[idx] = Ua[(size_t)(u0 + (idx >> 9)) * UU + (idx & 511)];
    }
    V_s[tid] = V[tid];
    bar_sync(&g_gcnt, &g_ggen, NCTA);

    for (int t = 0; t < TT; t++) {
        // ========================= Phase A =========================
        // prefetch h_{t-1} -> hz (swizzled) while attention runs
        {
            const float4* h4 = (const float4*)g_hbuf;
            #pragma unroll
            for (int i = 0; i < 8; i++) {
                int idx4 = tid + i * 512;
                int b  = idx4 >> 7;
                int k0 = (idx4 & 127) << 2;
                uint32_t dst = hz_u32 + (b * 1024 + (k0 ^ ((b & 7) << 2))) * 4;
                cp_async16(dst, h4 + idx4);
            }
            asm volatile("cp.async.commit_group;\n" ::: "memory");
        }

        // assemble hU slice [pr*128, pr*128+128) for batch pb from partials
        {
            int jj = pr * 128 + (tid & 127);
            int c0 = (tid >> 7) * 32;
            const float* pp = g_hUp + (size_t)(c0 * 32 + pb) * UU + jj;
            float s = 0.f;
            #pragma unroll 8
            for (int c = 0; c < 32; c++)
                s += pp[(size_t)c * (BB * UU)];
            sred[tid] = s;
            __syncthreads();
            if (tid < 128) {
                float v = sred[tid] + sred[tid+128] + sred[tid+256] + sred[tid+384];
                g_hU[pb * UU + pr * 128 + tid] = my_tanh(v);
            }
        }
        bar_sync(&g_lcnt[pb], &g_lgen[pb], 4u);

        // scores for t-chunk [pr*32, pr*32+32), tanh addition formula
        pair_s[tid] = make_float2(g_hU[pb * UU + tid], V_s[tid]);
        __syncthreads();
        {
            int t0 = pr * 32 + wid * 2;
            const float4* ax0 = (const float4*)(g_attx + (size_t)(pb * TT + t0) * UU);
            const float4* ax1 = ax0 + 128;
            float a0 = 0.f, a1 = 0.f;
            #pragma unroll
            for (int i = 0; i < 4; i++) {
                int u4 = i * 32 + lane;
                float4 t0v = ax0[u4], t1v = ax1[u4];
                float2 p0 = pair_s[u4*4+0], p1 = pair_s[u4*4+1];
                float2 p2 = pair_s[u4*4+2], p3 = pair_s[u4*4+3];
                a0 = fmaf(__fdividef(t0v.x + p0.x, fmaf(t0v.x, p0.x, 1.f)), p0.y, a0);
                a0 = fmaf(__fdividef(t0v.y + p1.x, fmaf(t0v.y, p1.x, 1.f)), p1.y, a0);
                a0 = fmaf(__fdividef(t0v.z + p2.x, fmaf(t0v.z, p2.x, 1.f)), p2.y, a0);
                a0 = fmaf(__fdividef(t0v.w + p3.x, fmaf(t0v.w, p3.x, 1.f)), p3.y, a0);
                a1 = fmaf(__fdividef(t1v.x + p0.x, fmaf(t1v.x, p0.x, 1.f)), p0.y, a1);
                a1 = fmaf(__fdividef(t1v.y + p1.x, fmaf(t1v.y, p1.x, 1.f)), p1.y, a1);
                a1 = fmaf(__fdividef(t1v.z + p2.x, fmaf(t1v.z, p2.x, 1.f)), p2.y, a1);
                a1 = fmaf(__fdividef(t1v.w + p3.x, fmaf(t1v.w, p3.x, 1.f)), p3.y, a1);
            }
            #pragma unroll
            for (int off = 16; off; off >>= 1) {
                a0 += __shfl_xor_sync(0xffffffffu, a0, off);
                a1 += __shfl_xor_sync(0xffffffffu, a1, off);
            }
            if (lane == 0) {
                g_sc[pb * TT + t0]     = a0;
                g_sc[pb * TT + t0 + 1] = a1;
            }
        }
        bar_sync(&g_lcnt[pb], &g_lgen[pb], 4u);

        // softmax over T (redundant x4) + z chunk [pr*128, pr*128+128)
        {
            float sv = -1e30f;
            if (tid < 128) sv = g_sc[pb * TT + tid];
            float mv = sv;
            #pragma unroll
            for (int off = 16; off; off >>= 1)
                mv = fmaxf(mv, __shfl_xor_sync(0xffffffffu, mv, off));
            if (lane == 0 && wid < 4) wr[wid] = mv;
            __syncthreads();
            float mx = fmaxf(fmaxf(wr[0], wr[1]), fmaxf(wr[2], wr[3]));
            float e = (tid < 128) ? __expf(sv - mx) : 0.f;
            float es = e;
            #pragma unroll
            for (int off = 16; off; off >>= 1)
                es += __shfl_xor_sync(0xffffffffu, es, off);
            if (lane == 0 && wid < 4) wr[4 + wid] = es;
            __syncthreads();
            float tot = wr[4] + wr[5] + wr[6] + wr[7];
            if (tid < 128) al_s[tid] = e * __fdividef(1.f, tot);
            __syncthreads();

            int c4 = tid & 31;
            int tg = tid >> 5;
            const float4* x4 = (const float4*)(x + (size_t)pb * TT * DD + pr * 128);
            float4 zp = make_float4(0.f, 0.f, 0.f, 0.f);
            #pragma unroll
            for (int j = 0; j < 8; j++) {
                int ts = tg * 8 + j;
                float av = al_s[ts];
                float4 xv = x4[(size_t)ts * 128 + c4];
                zp.x = fmaf(av, xv.x, zp.x); zp.y = fmaf(av, xv.y, zp.y);
                zp.z = fmaf(av, xv.z, zp.z); zp.w = fmaf(av, xv.w, zp.w);
            }
            zred4[tg * 32 + c4] = zp;
            __syncthreads();
            if (tid < 32) {
                float4 s = zred4[tid];
                #pragma unroll
                for (int k = 1; k < 16; k++) {
                    float4 v = zred4[k * 32 + tid];
                    s.x += v.x; s.y += v.y; s.z += v.z; s.w += v.w;
                }
                ((float4*)(g_z + pb * DD + pr * 128))[tid] = s;
            }
        }
        bar_sync(&g_gcnt, &g_ggen, NCTA);

        // ========================= Phase B =========================
        {
            float xkv;
            {
                int b = tid >> 4, ci = tid & 15;
                int col = ((ci >> 2) << 9) + u0 + (ci & 3);
                xkv = g_xk[((size_t)(b * TT) + t) * G4 + col];
            }
            // stage z (h already arriving via cp.async)
            const float4* z4 = (const float4*)g_z;
            #pragma unroll
            for (int i = 0; i < 8; i++) {
                int idx4 = tid + i * 512;
                int b  = idx4 >> 7;
                int k0 = ((idx4 & 127) << 2) + 512;
                float4 v = z4[idx4];
                *(float4*)&hz[b * 1024 + (k0 ^ ((b & 7) << 2))] = v;
            }
            asm volatile("cp.async.wait_group 0;\n" ::: "memory");
            __syncthreads();

            int ks  = tid >> 6;
            int bq  = (tid >> 2) & 15;
            int ciq = tid & 3;
            int b0 = bq * 2, b1 = b0 + 1;
            int m0 = (b0 & 7) << 2, m1 = (b1 & 7) << 2;
            const float* hp0 = &hz[b0 * 1024];
            const float* hp1 = &hz[b1 * 1024];
            const float* wp  = &W_s[ciq * 4];
            float a00=0,a01=0,a02=0,a03=0, a10=0,a11=0,a12=0,a13=0;
            int kb = ks * 128;
            #pragma unroll 4
            for (int k2 = 0; k2 < 64; k2++) {
                int k = kb + k2 * 2;
                float2 hv0 = *(const float2*)&hp0[k ^ m0];
                float2 hv1 = *(const float2*)&hp1[k ^ m1];
                float4 w0 = *(const float4*)&wp[k * 16];
                float4 w1 = *(const float4*)&wp[(k + 1) * 16];
                a00 = fmaf(hv0.x, w0.x, a00); a01 = fmaf(hv0.x, w0.y, a01);
                a02 = fmaf(hv0.x, w0.z, a02); a03 = fmaf(hv0.x, w0.w, a03);
                a10 = fmaf(hv1.x, w0.x, a10); a11 = fmaf(hv1.x, w0.y, a11);
                a12 = fmaf(hv1.x, w0.z, a12); a13 = fmaf(hv1.x, w0.w, a13);
                a00 = fmaf(hv0.y, w1.x, a00); a01 = fmaf(hv0.y, w1.y, a01);
                a02 = fmaf(hv0.y, w1.z, a02); a03 = fmaf(hv0.y, w1.w, a03);
                a10 = fmaf(hv1.y, w1.x, a10); a11 = fmaf(hv1.y, w1.y, a11);
                a12 = fmaf(hv1.y, w1.z, a12); a13 = fmaf(hv1.y, w1.w, a13);
            }
            __syncthreads();
            float* red = Asc;             // 8 x 512 partials
            *(float4*)&red[ks * 512 + b0 * 16 + ciq * 4] =
                make_float4(a00, a01, a02, a03);
            *(float4*)&red[ks * 512 + b1 * 16 + ciq * 4] =
                make_float4(a10, a11, a12, a13);
            __syncthreads();
            {
                float g = xkv;
                #pragma unroll
                for (int s2 = 0; s2 < 8; s2++) g += red[s2 * 512 + tid];
                gate_s[tid] = g;
            }
            __syncthreads();
            if (tid < 128) {
                int b = tid >> 2, jj = tid & 3;
                float gi = hsig(gate_s[b * 16 + 0  + jj]);
                float gf = hsig(gate_s[b * 16 + 4  + jj]);
                float gg = my_tanh(gate_s[b * 16 + 8  + jj]);
                float go = hsig(gate_s[b * 16 + 12 + jj]);
                float cn = gf * c_s[tid] + gi * gg;
                c_s[tid] = cn;
                float hn = go * my_tanh(cn);
                hnew_s[tid] = hn;
                int idx = b * UU + u0 + jj;
                g_hbuf[idx] = hn;
                out[((size_t)b * TT + t) * UU + u0 + jj] = hn;
            }
            __syncthreads();

            // rank-4 hU partial: h_new_tile @ Ua[u0:u0+4, :]
            {
                int b  = tid >> 4;
                int j0 = (tid & 15) * 32;
                float hv0 = hnew_s[b * 4 + 0];
                float hv1 = hnew_s[b * 4 + 1];
                float hv2 = hnew_s[b * 4 + 2];
                float hv3 = hnew_s[b * 4 + 3];
                float4* dst = (float4*)(g_hUp + ((size_t)bid * BB + b) * UU + j0);
                #pragma unroll
                for (int jq = 0; jq < 8; jq++) {
                    int j = j0 + jq * 4;
                    float4 r0 = *(const float4*)&Ua2_s[0*512 + j];
                    float4 r1 = *(const float4*)&Ua2_s[1*512 + j];
                    float4 r2 = *(const float4*)&Ua2_s[2*512 + j];
                    float4 r3 = *(const float4*)&Ua2_s[3*512 + j];
                    float4 o;
                    o.x = fmaf(hv3, r3.x, fmaf(hv2, r2.x, fmaf(hv1, r1.x, hv0 * r0.x)));
                    o.y = fmaf(hv3, r3.y, fmaf(hv2, r2.y, fmaf(hv1, r1.y, hv0 * r0.y)));
                    o.z = fmaf(hv3, r3.z, fmaf(hv2, r2.z, fmaf(hv1, r1.z, hv0 * r0.z)));
                    o.w = fmaf(hv3, r3.w, fmaf(hv2, r2.w, fmaf(hv1, r1.w, hv0 * r0.w)));
                    dst[jq] = o;
                }
            }
        }
        bar_sync(&g_gcnt, &g_ggen, NCTA);
    }
}

// ---------------------------------------------------------------------------
extern "C" void kernel_launch(void* const* d_in, const int* in_sizes, int n_in,
                              void* d_out, int out_size) {
    const float* x    = (const float*)d_in[0];
    const float* Wk   = (const float*)d_in[1];  // kernel (D,4U)
    const float* R    = (const float*)d_in[2];  // recurrent_kernel (U,4U)
    const float* A    = (const float*)d_in[3];  // attention_kernel (D,4U)
    const float* Wa   = (const float*)d_in[4];  // attention_W (D,U)
    const float* Ua   = (const float*)d_in[5];  // attention_U (U,U)
    const float* V    = (const float*)d_in[6];  // attention_V (U,1)
    const float* bias = (const float*)d_in[7];  // (4U)
    const float* ab   = (const float*)d_in[8];  // attention_b (U)
    float* out = (float*)d_out;

    const int SCAN_SMEM = 56576 * 4;  // 226304 B
    cudaFuncSetAttribute(k_scan, cudaFuncAttributeMaxDynamicSharedMemorySize,
                         SCAN_SMEM);

    k_pre<<<dim3(40, 32), 256>>>(x, Wk, Wa, bias, ab);
    k_scan<<<NCTA, NTHR, SCAN_SMEM>>>(x, R, A, Ua, V, out);
}

// round 14
// speedup vs baseline: 1.6154x; 1.6154x over previous
#include <cuda_runtime.h>
#include <cstdint>

#define BB 32
#define TT 128
#define DD 512
#define UU 512
#define G4 2048
#define NCTA 128
#define NTHR 512

// ---------------- scratch (device globals: allocation-free) ----------------
__device__ float g_attx[BB*TT*UU];      // 8 MB   tanh(x@W_att + b_att)
__device__ float g_xk  [BB*TT*G4];      // 32 MB  x@kernel + bias
__device__ float g_hbuf[BB*UU];         // hidden state
__device__ float g_z   [BB*DD];
__device__ float g_scp [BB*4*TT];       // per-(pb,pr) partial scores
__device__ unsigned g_gcnt, g_ggen;          // grid barrier
__device__ unsigned g_lcnt[BB], g_lgen[BB];  // per-batch 4-CTA barriers

__device__ __forceinline__ float my_tanh(float x) {
    x = fminf(fmaxf(x, -15.f), 15.f);
    float e = __expf(2.f * x);
    return __fdividef(e - 1.f, e + 1.f);
}
__device__ __forceinline__ float hsig(float x) {
    return fminf(fmaxf(0.2f * x + 0.5f, 0.f), 1.f);
}

// Software barrier. Safe: all participating CTAs co-resident (1 CTA/SM,
// 128 <= 148 SMs). __threadfence publishes prior writes and invalidates L1.
__device__ __forceinline__ void bar_sync(unsigned* cnt, unsigned* gen, unsigned n) {
    __syncthreads();
    if (threadIdx.x == 0) {
        __threadfence();
        unsigned my = *(volatile unsigned*)gen;
        if (atomicAdd(cnt, 1u) == n - 1u) {
            *cnt = 0u;
            __threadfence();
            atomicAdd(gen, 1u);
        } else {
            while (*(volatile unsigned*)gen == my) { }
        }
        __threadfence();
    }
    __syncthreads();
}

__device__ __forceinline__ void cp_async16(uint32_t dst_smem, const void* src) {
    asm volatile("cp.async.ca.shared.global [%0], [%1], 16;\n"
                 :: "r"(dst_smem), "l"(src));
}

// ---------------- precompute: one SGEMM over virtual N = 2048 + 512 --------
// n<2048 -> g_xk = X@kernel + bias ; n>=2048 -> g_attx = tanh(X@W_att + ab)
__global__ void __launch_bounds__(256) k_pre(
        const float* __restrict__ x, const float* __restrict__ Wk,
        const float* __restrict__ Wa, const float* __restrict__ bias,
        const float* __restrict__ ab) {
    __shared__ float As[16][132];
    __shared__ float Bs[16][64];
    int m0 = blockIdx.y * 128;
    int n0 = blockIdx.x * 64;
    bool isK = (n0 < G4);
    const float* Wm = isK ? Wk : Wa;
    int ldw = isK ? G4 : UU;
    int nc0 = isK ? n0 : (n0 - G4);
    int tid = threadIdx.x;
    int tm = (tid >> 4) * 8;
    int tn = (tid & 15) * 4;
    float acc[8][4];
    #pragma unroll
    for (int i = 0; i < 8; i++)
        #pragma unroll
        for (int j = 0; j < 4; j++) acc[i][j] = 0.f;

    for (int k0 = 0; k0 < DD; k0 += 16) {
        #pragma unroll
        for (int i = 0; i < 2; i++) {
            int idx = tid + i * 256;
            int row = idx >> 2;
            int c4  = (idx & 3) * 4;
            float4 v = *(const float4*)(x + (size_t)(m0 + row) * DD + k0 + c4);
            As[c4+0][row] = v.x; As[c4+1][row] = v.y;
            As[c4+2][row] = v.z; As[c4+3][row] = v.w;
        }
        {
            int row = tid >> 4;
            int c4  = (tid & 15) * 4;
            *(float4*)&Bs[row][c4] =
                *(const float4*)(Wm + (size_t)(k0 + row) * ldw + nc0 + c4);
        }
        __syncthreads();
        #pragma unroll
        for (int kk = 0; kk < 16; kk++) {
            float4 a0 = *(float4*)&As[kk][tm];
            float4 a1 = *(float4*)&As[kk][tm + 4];
            float4 bv = *(float4*)&Bs[kk][tn];
            float am[8] = {a0.x,a0.y,a0.z,a0.w,a1.x,a1.y,a1.z,a1.w};
            float bn[4] = {bv.x,bv.y,bv.z,bv.w};
            #pragma unroll
            for (int i = 0; i < 8; i++)
                #pragma unroll
                for (int j = 0; j < 4; j++)
                    acc[i][j] = fmaf(am[i], bn[j], acc[i][j]);
        }
        __syncthreads();
    }
    const float* bvec = isK ? bias : ab;
    float bj[4];
    #pragma unroll
    for (int j = 0; j < 4; j++) bj[j] = bvec[nc0 + tn + j];
    #pragma unroll
    for (int i = 0; i < 8; i++) {
        int m = m0 + tm + i;
        if (isK) {
            float* dst = g_xk + (size_t)m * G4 + nc0 + tn;
            #pragma unroll
            for (int j = 0; j < 4; j++) dst[j] = acc[i][j] + bj[j];
        } else {
            float* dst = g_attx + (size_t)m * UU + nc0 + tn;
            #pragma unroll
            for (int j = 0; j < 4; j++) dst[j] = my_tanh(acc[i][j] + bj[j]);
        }
    }
}

// ---------------- persistent scan kernel ------------------------------------
// 128 CTAs x 512 thr, 1 CTA/SM, ~215 KB smem.
// Phase A (CTA=(pb,pr)): cp.async prefetch h->hz (for B); hU slice (local,
//   Ua from L2) -> partial scores over own u-slice for ALL 128 t (local!)
//   -> lbar4 -> combine + softmax (redundant x4) + z slice.       [grid bar]
// Phase B (CTA=u-tile): stage z; gates = xk + [h;z]@[R;A] (conflict-free
//   swizzle); LSTM pointwise (c in smem).                         [grid bar]
__global__ void __launch_bounds__(NTHR, 1) k_scan(
        const float* __restrict__ x,  const float* __restrict__ R,
        const float* __restrict__ A,  const float* __restrict__ Ua,
        const float* __restrict__ V,  float* __restrict__ out) {
    extern __shared__ float sm[];
    float* W_s    = sm;               // 16384
    float* hz     = sm + 16384;       // 32768 (dedicated)
    float* Asc    = sm + 49152;       // 4096 (A scratch / B reduction)
    float* V_s    = sm + 53248;       // 512
    float* gate_s = sm + 53760;       // 512
    float* c_s    = sm + 54272;       // 128
    float* h_s    = sm + 54400;       // 512
    // total 54912 floats = 219648 B

    float2* pair_s = (float2*)Asc;            // 128 float2 (256 floats)
    float4* hred4  = (float4*)(Asc + 256);    // 2048 floats (A1)
    float4* zred4  = (float4*)(Asc + 256);    // alias (A3, disjoint in time)
    float*  al_s   = Asc + 2304;              // 128
    float*  wr     = Asc + 2432;              // 8

    const int bid = blockIdx.x;
    const int tid = threadIdx.x;
    const int u0  = bid * 4;                  // Phase B u-tile
    const int wid = tid >> 5, lane = tid & 31;
    const int pb  = bid >> 2, pr = bid & 3;   // Phase A role
    const uint32_t hz_u32 = (uint32_t)__cvta_generic_to_shared(hz);

    // ---- one-time init ----
    if (tid < 128) {
        g_hbuf[bid * 128 + tid] = 0.f;
        c_s[tid] = 0.f;
    }
    #pragma unroll 4
    for (int i = 0; i < 32; i++) {            // gate weights [R;A]
        int idx = tid + i * 512;
        int k = idx >> 4, ci = idx & 15;
        int col = ((ci >> 2) << 9) + u0 + (ci & 3);
        W_s[idx] = (k < 512) ? R[(size_t)k * G4 + col]
                             : A[(size_t)(k - 512) * G4 + col];
    }
    V_s[tid] = V[tid];
    bar_sync(&g_gcnt, &g_ggen, NCTA);

    for (int t = 0; t < TT; t++) {
        // ========================= Phase A =========================
        // prefetch h_{t-1} -> hz (swizzled) for Phase B
        {
            const float4* h4 = (const float4*)g_hbuf;
            #pragma unroll
            for (int i = 0; i < 8; i++) {
                int idx4 = tid + i * 512;
                int b  = idx4 >> 7;
                int k0 = (idx4 & 127) << 2;
                uint32_t dst = hz_u32
                    + (b * 1024 + (k0 ^ (((b >> 1) & 7) << 2))) * 4;
                cp_async16(dst, h4 + idx4);
            }
            asm volatile("cp.async.commit_group;\n" ::: "memory");
        }

        // A1: hU slice tanh( h[pb,:] @ Ua[:, pr*128 .. +128) ), kept in smem
        h_s[tid] = g_hbuf[pb * UU + tid];
        __syncthreads();
        {
            int c4 = tid & 31;            // float4 col in 128-col slice
            int ks = tid >> 5;            // 0..15, 32 k each
            const float4* up = (const float4*)Ua
                               + (size_t)(ks * 32) * 128 + pr * 32 + c4;
            float4 a = make_float4(0.f, 0.f, 0.f, 0.f);
            #pragma unroll 8
            for (int j = 0; j < 32; j++) {
                float hv = h_s[ks * 32 + j];
                float4 w = up[(size_t)j * 128];
                a.x = fmaf(hv, w.x, a.x); a.y = fmaf(hv, w.y, a.y);
                a.z = fmaf(hv, w.z, a.z); a.w = fmaf(hv, w.w, a.w);
            }
            hred4[ks * 32 + c4] = a;
        }
        __syncthreads();
        if (tid < 32) {
            float4 s = hred4[tid];
            #pragma unroll
            for (int k = 1; k < 16; k++) {
                float4 v = hred4[k * 32 + tid];
                s.x += v.x; s.y += v.y; s.z += v.z; s.w += v.w;
            }
            int ub = pr * 128 + tid * 4;
            pair_s[tid*4+0] = make_float2(my_tanh(s.x), V_s[ub+0]);
            pair_s[tid*4+1] = make_float2(my_tanh(s.y), V_s[ub+1]);
            pair_s[tid*4+2] = make_float2(my_tanh(s.z), V_s[ub+2]);
            pair_s[tid*4+3] = make_float2(my_tanh(s.w), V_s[ub+3]);
        }
        __syncthreads();

        // A2: partial scores over OWN u-slice for ALL 128 timesteps (local)
        {
            float2 q0 = pair_s[lane*4+0], q1 = pair_s[lane*4+1];
            float2 q2 = pair_s[lane*4+2], q3 = pair_s[lane*4+3];
            const float4* ax = (const float4*)g_attx;
            float p[8];
            #pragma unroll
            for (int i = 0; i < 8; i++) p[i] = 0.f;
            #pragma unroll
            for (int tt = 0; tt < 8; tt++) {
                int tp = wid + tt * 16;
                float4 av = ax[((size_t)(pb * TT + tp)) * 128 + pr * 32 + lane];
                p[tt] = fmaf(__fdividef(av.x + q0.x, fmaf(av.x, q0.x, 1.f)), q0.y, p[tt]);
                p[tt] = fmaf(__fdividef(av.y + q1.x, fmaf(av.y, q1.x, 1.f)), q1.y, p[tt]);
                p[tt] = fmaf(__fdividef(av.z + q2.x, fmaf(av.z, q2.x, 1.f)), q2.y, p[tt]);
                p[tt] = fmaf(__fdividef(av.w + q3.x, fmaf(av.w, q3.x, 1.f)), q3.y, p[tt]);
            }
            #pragma unroll
            for (int tt = 0; tt < 8; tt++) {
                #pragma unroll
                for (int off = 16; off; off >>= 1)
                    p[tt] += __shfl_xor_sync(0xffffffffu, p[tt], off);
            }
            if (lane == 0) {
                #pragma unroll
                for (int tt = 0; tt < 8; tt++)
                    g_scp[(pb * 4 + pr) * TT + wid + tt * 16] = p[tt];
            }
        }
        bar_sync(&g_lcnt[pb], &g_lgen[pb], 4u);

        // A3: combine partials + softmax over T (redundant x4) + z slice
        {
            float sv = -1e30f;
            if (tid < 128) {
                sv = g_scp[(pb * 4 + 0) * TT + tid]
                   + g_scp[(pb * 4 + 1) * TT + tid]
                   + g_scp[(pb * 4 + 2) * TT + tid]
                   + g_scp[(pb * 4 + 3) * TT + tid];
            }
            float mv = sv;
            #pragma unroll
            for (int off = 16; off; off >>= 1)
                mv = fmaxf(mv, __shfl_xor_sync(0xffffffffu, mv, off));
            if (lane == 0 && wid < 4) wr[wid] = mv;
            __syncthreads();
            float mx = fmaxf(fmaxf(wr[0], wr[1]), fmaxf(wr[2], wr[3]));
            float e = (tid < 128) ? __expf(sv - mx) : 0.f;
            float es = e;
            #pragma unroll
            for (int off = 16; off; off >>= 1)
                es += __shfl_xor_sync(0xffffffffu, es, off);
            if (lane == 0 && wid < 4) wr[4 + wid] = es;
            __syncthreads();
            float tot = wr[4] + wr[5] + wr[6] + wr[7];
            if (tid < 128) al_s[tid] = e * __fdividef(1.f, tot);
            __syncthreads();

            int c4 = tid & 31;
            int tg = tid >> 5;
            const float4* x4 = (const float4*)(x + (size_t)pb * TT * DD + pr * 128);
            float4 zp = make_float4(0.f, 0.f, 0.f, 0.f);
            #pragma unroll
            for (int j = 0; j < 8; j++) {
                int ts = tg * 8 + j;
                float av = al_s[ts];
                float4 xv = x4[(size_t)ts * 128 + c4];
                zp.x = fmaf(av, xv.x, zp.x); zp.y = fmaf(av, xv.y, zp.y);
                zp.z = fmaf(av, xv.z, zp.z); zp.w = fmaf(av, xv.w, zp.w);
            }
            zred4[tg * 32 + c4] = zp;
            __syncthreads();
            if (tid < 32) {
                float4 s = zred4[tid];
                #pragma unroll
                for (int k = 1; k < 16; k++) {
                    float4 v = zred4[k * 32 + tid];
                    s.x += v.x; s.y += v.y; s.z += v.z; s.w += v.w;
                }
                ((float4*)(g_z + pb * DD + pr * 128))[tid] = s;
            }
        }
        bar_sync(&g_gcnt, &g_ggen, NCTA);

        // ========================= Phase B =========================
        {
            float xkv;
            {
                int b = tid >> 4, ci = tid & 15;
                int col = ((ci >> 2) << 9) + u0 + (ci & 3);
                xkv = g_xk[((size_t)(b * TT) + t) * G4 + col];
            }
            // stage z (h already arriving via cp.async)
            const float4* z4 = (const float4*)g_z;
            #pragma unroll
            for (int i = 0; i < 8; i++) {
                int idx4 = tid + i * 512;
                int b  = idx4 >> 7;
                int k0 = ((idx4 & 127) << 2) + 512;
                float4 v = z4[idx4];
                *(float4*)&hz[b * 1024 + (k0 ^ (((b >> 1) & 7) << 2))] = v;
            }
            asm volatile("cp.async.wait_group 0;\n" ::: "memory");
            __syncthreads();

            int ks  = tid >> 6;
            int bq  = (tid >> 2) & 15;
            int ciq = tid & 3;
            int b0 = bq * 2, b1 = b0 + 1;
            int m0 = (bq & 7) << 2;       // = ((b0>>1)&7)<<2 = ((b1>>1)&7)<<2
            const float* hp0 = &hz[b0 * 1024];
            const float* hp1 = &hz[b1 * 1024];
            const float* wp  = &W_s[ciq * 4];
            float a00=0,a01=0,a02=0,a03=0, a10=0,a11=0,a12=0,a13=0;
            int kb = ks * 128;
            #pragma unroll 4
            for (int k2 = 0; k2 < 64; k2++) {
                int k = kb + k2 * 2;
                float2 hv0 = *(const float2*)&hp0[k ^ m0];
                float2 hv1 = *(const float2*)&hp1[k ^ m0];
                float4 w0 = *(const float4*)&wp[k * 16];
                float4 w1 = *(const float4*)&wp[(k + 1) * 16];
                a00 = fmaf(hv0.x, w0.x, a00); a01 = fmaf(hv0.x, w0.y, a01);
                a02 = fmaf(hv0.x, w0.z, a02); a03 = fmaf(hv0.x, w0.w, a03);
                a10 = fmaf(hv1.x, w0.x, a10); a11 = fmaf(hv1.x, w0.y, a11);
                a12 = fmaf(hv1.x, w0.z, a12); a13 = fmaf(hv1.x, w0.w, a13);
                a00 = fmaf(hv0.y, w1.x, a00); a01 = fmaf(hv0.y, w1.y, a01);
                a02 = fmaf(hv0.y, w1.z, a02); a03 = fmaf(hv0.y, w1.w, a03);
                a10 = fmaf(hv1.y, w1.x, a10); a11 = fmaf(hv1.y, w1.y, a11);
                a12 = fmaf(hv1.y, w1.z, a12); a13 = fmaf(hv1.y, w1.w, a13);
            }
            __syncthreads();
            float* red = Asc;             // 8 x 512 partials
            *(float4*)&red[ks * 512 + b0 * 16 + ciq * 4] =
                make_float4(a00, a01, a02, a03);
            *(float4*)&red[ks * 512 + b1 * 16 + ciq * 4] =
                make_float4(a10, a11, a12, a13);
            __syncthreads();
            {
                float g = xkv;
                #pragma unroll
                for (int s2 = 0; s2 < 8; s2++) g += red[s2 * 512 + tid];
                gate_s[tid] = g;
            }
            __syncthreads();
            if (tid < 128) {
                int b = tid >> 2, jj = tid & 3;
                float gi = hsig(gate_s[b * 16 + 0  + jj]);
                float gf = hsig(gate_s[b * 16 + 4  + jj]);
                float gg = my_tanh(gate_s[b * 16 + 8  + jj]);
                float go = hsig(gate_s[b * 16 + 12 + jj]);
                float cn = gf * c_s[tid] + gi * gg;
                c_s[tid] = cn;
                float hn = go * my_tanh(cn);
                int idx = b * UU + u0 + jj;
                g_hbuf[idx] = hn;
                out[((size_t)b * TT + t) * UU + u0 + jj] = hn;
            }
        }
        bar_sync(&g_gcnt, &g_ggen, NCTA);
    }
}

// ---------------------------------------------------------------------------
extern "C" void kernel_launch(void* const* d_in, const int* in_sizes, int n_in,
                              void* d_out, int out_size) {
    const float* x    = (const float*)d_in[0];
    const float* Wk   = (const float*)d_in[1];  // kernel (D,4U)
    const float* R    = (const float*)d_in[2];  // recurrent_kernel (U,4U)
    const float* A    = (const float*)d_in[3];  // attention_kernel (D,4U)
    const float* Wa   = (const float*)d_in[4];  // attention_W (D,U)
    const float* Ua   = (const float*)d_in[5];  // attention_U (U,U)
    const float* V    = (const float*)d_in[6];  // attention_V (U,1)
    const float* bias = (const float*)d_in[7];  // (4U)
    const float* ab   = (const float*)d_in[8];  // attention_b (U)
    float* out = (float*)d_out;

    const int SCAN_SMEM = 54912 * 4;  // 219648 B
    cudaFuncSetAttribute(k_scan, cudaFuncAttributeMaxDynamicSharedMemorySize,
                         SCAN_SMEM);

    k_pre<<<dim3(40, 32), 256>>>(x, Wk, Wa, bias, ab);
    k_scan<<<NCTA, NTHR, SCAN_SMEM>>>(x, R, A, Ua, V, out);
}

// round 15
// speedup vs baseline: 1.6270x; 1.0072x over previous
#include <cuda_runtime.h>
#include <cstdint>

#define BB 32
#define TT 128
#define DD 512
#define UU 512
#define G4 2048
#define NCTA 128
#define NTHR 512

typedef unsigned long long ull;

// ---------------- packed fp32x2 helpers (sm_103a FFMA2 path) ---------------
__device__ __forceinline__ ull dup2(float x) {
    ull r; asm("mov.b64 %0, {%1, %1};" : "=l"(r) : "f"(x)); return r;
}
__device__ __forceinline__ void upk2(ull v, float& x, float& y) {
    asm("mov.b64 {%0, %1}, %2;" : "=f"(x), "=f"(y) : "l"(v));
}
__device__ __forceinline__ ull ffma2(ull a, ull b, ull c) {
    ull d; asm("fma.rn.f32x2 %0, %1, %2, %3;" : "=l"(d) : "l"(a), "l"(b), "l"(c));
    return d;
}

// ---------------- scratch (device globals: allocation-free) ----------------
__device__ float g_attx[BB*TT*UU];      // 8 MB   tanh(x@W_att + b_att)
__device__ float g_xk  [BB*TT*G4];      // 32 MB  x@kernel + bias
__device__ float g_hbuf[BB*UU];         // hidden state
__device__ float g_z   [BB*DD];
__device__ float g_scp [BB*4*TT];       // per-(pb,pr) partial scores
__device__ unsigned g_gcnt, g_ggen;          // grid barrier
__device__ unsigned g_lcnt[BB], g_lgen[BB];  // per-batch 4-CTA barriers

__device__ __forceinline__ float my_tanh(float x) {
    x = fminf(fmaxf(x, -15.f), 15.f);
    float e = __expf(2.f * x);
    return __fdividef(e - 1.f, e + 1.f);
}
__device__ __forceinline__ float hsig(float x) {
    return fminf(fmaxf(0.2f * x + 0.5f, 0.f), 1.f);
}

// Software barrier. Safe: all participating CTAs co-resident (1 CTA/SM,
// 128 <= 148 SMs). __threadfence publishes prior writes and invalidates L1.
__device__ __forceinline__ void bar_sync(unsigned* cnt, unsigned* gen, unsigned n) {
    __syncthreads();
    if (threadIdx.x == 0) {
        __threadfence();
        unsigned my = *(volatile unsigned*)gen;
        if (atomicAdd(cnt, 1u) == n - 1u) {
            *cnt = 0u;
            __threadfence();
            atomicAdd(gen, 1u);
        } else {
            while (*(volatile unsigned*)gen == my) { }
        }
        __threadfence();
    }
    __syncthreads();
}

__device__ __forceinline__ void cp_async16(uint32_t dst_smem, const void* src) {
    asm volatile("cp.async.ca.shared.global [%0], [%1], 16;\n"
                 :: "r"(dst_smem), "l"(src));
}

// ---------------- precompute: one SGEMM over virtual N = 2048 + 512 --------
// n<2048 -> g_xk = X@kernel + bias ; n>=2048 -> g_attx = tanh(X@W_att + ab)
__global__ void __launch_bounds__(256) k_pre(
        const float* __restrict__ x, const float* __restrict__ Wk,
        const float* __restrict__ Wa, const float* __restrict__ bias,
        const float* __restrict__ ab) {
    __shared__ float As[16][132];
    __shared__ float Bs[16][64];
    int m0 = blockIdx.y * 128;
    int n0 = blockIdx.x * 64;
    bool isK = (n0 < G4);
    const float* Wm = isK ? Wk : Wa;
    int ldw = isK ? G4 : UU;
    int nc0 = isK ? n0 : (n0 - G4);
    int tid = threadIdx.x;
    int tm = (tid >> 4) * 8;
    int tn = (tid & 15) * 4;
    ull acc2[8][2];
    #pragma unroll
    for (int i = 0; i < 8; i++) { acc2[i][0] = 0ull; acc2[i][1] = 0ull; }

    for (int k0 = 0; k0 < DD; k0 += 16) {
        #pragma unroll
        for (int i = 0; i < 2; i++) {
            int idx = tid + i * 256;
            int row = idx >> 2;
            int c4  = (idx & 3) * 4;
            float4 v = *(const float4*)(x + (size_t)(m0 + row) * DD + k0 + c4);
            As[c4+0][row] = v.x; As[c4+1][row] = v.y;
            As[c4+2][row] = v.z; As[c4+3][row] = v.w;
        }
        {
            int row = tid >> 4;
            int c4  = (tid & 15) * 4;
            *(float4*)&Bs[row][c4] =
                *(const float4*)(Wm + (size_t)(k0 + row) * ldw + nc0 + c4);
        }
        __syncthreads();
        #pragma unroll
        for (int kk = 0; kk < 16; kk++) {
            float4 a0 = *(float4*)&As[kk][tm];
            float4 a1 = *(float4*)&As[kk][tm + 4];
            ulonglong2 bp = *(const ulonglong2*)&Bs[kk][tn];
            float am[8] = {a0.x,a0.y,a0.z,a0.w,a1.x,a1.y,a1.z,a1.w};
            #pragma unroll
            for (int i = 0; i < 8; i++) {
                ull ad = dup2(am[i]);
                acc2[i][0] = ffma2(ad, bp.x, acc2[i][0]);
                acc2[i][1] = ffma2(ad, bp.y, acc2[i][1]);
            }
        }
        __syncthreads();
    }
    const float* bvec = isK ? bias : ab;
    float bj[4];
    #pragma unroll
    for (int j = 0; j < 4; j++) bj[j] = bvec[nc0 + tn + j];
    #pragma unroll
    for (int i = 0; i < 8; i++) {
        int m = m0 + tm + i;
        float c0, c1, c2, c3;
        upk2(acc2[i][0], c0, c1);
        upk2(acc2[i][1], c2, c3);
        float cv[4] = {c0, c1, c2, c3};
        if (isK) {
            float* dst = g_xk + (size_t)m * G4 + nc0 + tn;
            #pragma unroll
            for (int j = 0; j < 4; j++) dst[j] = cv[j] + bj[j];
        } else {
            float* dst = g_attx + (size_t)m * UU + nc0 + tn;
            #pragma unroll
            for (int j = 0; j < 4; j++) dst[j] = my_tanh(cv[j] + bj[j]);
        }
    }
}

// ---------------- persistent scan kernel ------------------------------------
// 128 CTAs x 512 thr, 1 CTA/SM, ~215 KB smem. Same structure as round 14;
// inner GEMMs converted to packed fp32x2 FFMA2.
__global__ void __launch_bounds__(NTHR, 1) k_scan(
        const float* __restrict__ x,  const float* __restrict__ R,
        const float* __restrict__ A,  const float* __restrict__ Ua,
        const float* __restrict__ V,  float* __restrict__ out) {
    extern __shared__ float sm[];
    float* W_s    = sm;               // 16384
    float* hz     = sm + 16384;       // 32768 (dedicated)
    float* Asc    = sm + 49152;       // 4096 (A scratch / B reduction)
    float* V_s    = sm + 53248;       // 512
    float* gate_s = sm + 53760;       // 512
    float* c_s    = sm + 54272;       // 128
    float* h_s    = sm + 54400;       // 512
    // total 54912 floats = 219648 B

    float2* pair_s = (float2*)Asc;            // 128 float2 (256 floats)
    float4* hred4  = (float4*)(Asc + 256);    // 2048 floats (A1)
    float4* zred4  = (float4*)(Asc + 256);    // alias (A3, disjoint in time)
    float*  al_s   = Asc + 2304;              // 128
    float*  wr     = Asc + 2432;              // 8

    const int bid = blockIdx.x;
    const int tid = threadIdx.x;
    const int u0  = bid * 4;                  // Phase B u-tile
    const int wid = tid >> 5, lane = tid & 31;
    const int pb  = bid >> 2, pr = bid & 3;   // Phase A role
    const uint32_t hz_u32 = (uint32_t)__cvta_generic_to_shared(hz);

    // ---- one-time init ----
    if (tid < 128) {
        g_hbuf[bid * 128 + tid] = 0.f;
        c_s[tid] = 0.f;
    }
    #pragma unroll 4
    for (int i = 0; i < 32; i++) {            // gate weights [R;A]
        int idx = tid + i * 512;
        int k = idx >> 4, ci = idx & 15;
        int col = ((ci >> 2) << 9) + u0 + (ci & 3);
        W_s[idx] = (k < 512) ? R[(size_t)k * G4 + col]
                             : A[(size_t)(k - 512) * G4 + col];
    }
    V_s[tid] = V[tid];
    bar_sync(&g_gcnt, &g_ggen, NCTA);

    for (int t = 0; t < TT; t++) {
        // ========================= Phase A =========================
        // prefetch h_{t-1} -> hz (swizzled) for Phase B
        {
            const float4* h4 = (const float4*)g_hbuf;
            #pragma unroll
            for (int i = 0; i < 8; i++) {
                int idx4 = tid + i * 512;
                int b  = idx4 >> 7;
                int k0 = (idx4 & 127) << 2;
                uint32_t dst = hz_u32
                    + (b * 1024 + (k0 ^ (((b >> 1) & 7) << 2))) * 4;
                cp_async16(dst, h4 + idx4);
            }
            asm volatile("cp.async.commit_group;\n" ::: "memory");
        }

        // A1: hU slice tanh( h[pb,:] @ Ua[:, pr*128 .. +128) ), kept in smem
        h_s[tid] = g_hbuf[pb * UU + tid];
        __syncthreads();
        {
            int c4 = tid & 31;            // float4 col in 128-col slice
            int ks = tid >> 5;            // 0..15, 32 k each
            const ulonglong2* up = (const ulonglong2*)Ua
                               + (size_t)(ks * 32) * 128 + pr * 32 + c4;
            ull a01 = 0ull, a23 = 0ull;
            #pragma unroll 8
            for (int j = 0; j < 32; j++) {
                ull hd = dup2(h_s[ks * 32 + j]);
                ulonglong2 w = up[(size_t)j * 128];
                a01 = ffma2(hd, w.x, a01);
                a23 = ffma2(hd, w.y, a23);
            }
            float4 a;
            upk2(a01, a.x, a.y);
            upk2(a23, a.z, a.w);
            hred4[ks * 32 + c4] = a;
        }
        __syncthreads();
        if (tid < 32) {
            float4 s = hred4[tid];
            #pragma unroll
            for (int k = 1; k < 16; k++) {
                float4 v = hred4[k * 32 + tid];
                s.x += v.x; s.y += v.y; s.z += v.z; s.w += v.w;
            }
            int ub = pr * 128 + tid * 4;
            pair_s[tid*4+0] = make_float2(my_tanh(s.x), V_s[ub+0]);
            pair_s[tid*4+1] = make_float2(my_tanh(s.y), V_s[ub+1]);
            pair_s[tid*4+2] = make_float2(my_tanh(s.z), V_s[ub+2]);
            pair_s[tid*4+3] = make_float2(my_tanh(s.w), V_s[ub+3]);
        }
        __syncthreads();

        // A2: partial scores over OWN u-slice for ALL 128 timesteps (local)
        {
            float2 q0 = pair_s[lane*4+0], q1 = pair_s[lane*4+1];
            float2 q2 = pair_s[lane*4+2], q3 = pair_s[lane*4+3];
            const float4* ax = (const float4*)g_attx;
            float p[8];
            #pragma unroll
            for (int i = 0; i < 8; i++) p[i] = 0.f;
            #pragma unroll
            for (int tt = 0; tt < 8; tt++) {
                int tp = wid + tt * 16;
                float4 av = ax[((size_t)(pb * TT + tp)) * 128 + pr * 32 + lane];
                p[tt] = fmaf(__fdividef(av.x + q0.x, fmaf(av.x, q0.x, 1.f)), q0.y, p[tt]);
                p[tt] = fmaf(__fdividef(av.y + q1.x, fmaf(av.y, q1.x, 1.f)), q1.y, p[tt]);
                p[tt] = fmaf(__fdividef(av.z + q2.x, fmaf(av.z, q2.x, 1.f)), q2.y, p[tt]);
                p[tt] = fmaf(__fdividef(av.w + q3.x, fmaf(av.w, q3.x, 1.f)), q3.y, p[tt]);
            }
            #pragma unroll
            for (int tt = 0; tt < 8; tt++) {
                #pragma unroll
                for (int off = 16; off; off >>= 1)
                    p[tt] += __shfl_xor_sync(0xffffffffu, p[tt], off);
            }
            if (lane == 0) {
                #pragma unroll
                for (int tt = 0; tt < 8; tt++)
                    g_scp[(pb * 4 + pr) * TT + wid + tt * 16] = p[tt];
            }
        }
        bar_sync(&g_lcnt[pb], &g_lgen[pb], 4u);

        // A3: combine partials + softmax over T (redundant x4) + z slice
        {
            float sv = -1e30f;
            if (tid < 128) {
                sv = g_scp[(pb * 4 + 0) * TT + tid]
                   + g_scp[(pb * 4 + 1) * TT + tid]
                   + g_scp[(pb * 4 + 2) * TT + tid]
                   + g_scp[(pb * 4 + 3) * TT + tid];
            }
            float mv = sv;
            #pragma unroll
            for (int off = 16; off; off >>= 1)
                mv = fmaxf(mv, __shfl_xor_sync(0xffffffffu, mv, off));
            if (lane == 0 && wid < 4) wr[wid] = mv;
            __syncthreads();
            float mx = fmaxf(fmaxf(wr[0], wr[1]), fmaxf(wr[2], wr[3]));
            float e = (tid < 128) ? __expf(sv - mx) : 0.f;
            float es = e;
            #pragma unroll
            for (int off = 16; off; off >>= 1)
                es += __shfl_xor_sync(0xffffffffu, es, off);
            if (lane == 0 && wid < 4) wr[4 + wid] = es;
            __syncthreads();
            float tot = wr[4] + wr[5] + wr[6] + wr[7];
            if (tid < 128) al_s[tid] = e * __fdividef(1.f, tot);
            __syncthreads();

            int c4 = tid & 31;
            int tg = tid >> 5;
            const ulonglong2* x2 = (const ulonglong2*)(x + (size_t)pb * TT * DD + pr * 128);
            ull z01 = 0ull, z23 = 0ull;
            #pragma unroll
            for (int j = 0; j < 8; j++) {
                int ts = tg * 8 + j;
                ull ad = dup2(al_s[ts]);
                ulonglong2 xv = x2[(size_t)ts * 128 + c4];
                z01 = ffma2(ad, xv.x, z01);
                z23 = ffma2(ad, xv.y, z23);
            }
            float4 zp;
            upk2(z01, zp.x, zp.y);
            upk2(z23, zp.z, zp.w);
            zred4[tg * 32 + c4] = zp;
            __syncthreads();
            if (tid < 32) {
                float4 s = zred4[tid];
                #pragma unroll
                for (int k = 1; k < 16; k++) {
                    float4 v = zred4[k * 32 + tid];
                    s.x += v.x; s.y += v.y; s.z += v.z; s.w += v.w;
                }
                ((float4*)(g_z + pb * DD + pr * 128))[tid] = s;
            }
        }
        bar_sync(&g_gcnt, &g_ggen, NCTA);

        // ========================= Phase B =========================
        {
            float xkv;
            {
                int b = tid >> 4, ci = tid & 15;
                int col = ((ci >> 2) << 9) + u0 + (ci & 3);
                xkv = g_xk[((size_t)(b * TT) + t) * G4 + col];
            }
            // stage z (h already arriving via cp.async)
            const float4* z4 = (const float4*)g_z;
            #pragma unroll
            for (int i = 0; i < 8; i++) {
                int idx4 = tid + i * 512;
                int b  = idx4 >> 7;
                int k0 = ((idx4 & 127) << 2) + 512;
                float4 v = z4[idx4];
                *(float4*)&hz[b * 1024 + (k0 ^ (((b >> 1) & 7) << 2))] = v;
            }
            asm volatile("cp.async.wait_group 0;\n" ::: "memory");
            __syncthreads();

            int ks  = tid >> 6;
            int bq  = (tid >> 2) & 15;
            int ciq = tid & 3;
            int b0 = bq * 2, b1 = b0 + 1;
            int m0 = (bq & 7) << 2;       // = ((b0>>1)&7)<<2 = ((b1>>1)&7)<<2
            const float* hp0 = &hz[b0 * 1024];
            const float* hp1 = &hz[b1 * 1024];
            const float* wp  = &W_s[ciq * 4];
            ull A00 = 0ull, A01 = 0ull, A10 = 0ull, A11 = 0ull;
            int kb = ks * 128;
            #pragma unroll 4
            for (int k2 = 0; k2 < 64; k2++) {
                int k = kb + k2 * 2;
                float2 hv0 = *(const float2*)&hp0[k ^ m0];
                float2 hv1 = *(const float2*)&hp1[k ^ m0];
                ulonglong2 wv0 = *(const ulonglong2*)&wp[k * 16];
                ulonglong2 wv1 = *(const ulonglong2*)&wp[(k + 1) * 16];
                ull d00 = dup2(hv0.x), d01 = dup2(hv0.y);
                ull d10 = dup2(hv1.x), d11 = dup2(hv1.y);
                A00 = ffma2(d00, wv0.x, A00); A01 = ffma2(d00, wv0.y, A01);
                A10 = ffma2(d10, wv0.x, A10); A11 = ffma2(d10, wv0.y, A11);
                A00 = ffma2(d01, wv1.x, A00); A01 = ffma2(d01, wv1.y, A01);
                A10 = ffma2(d11, wv1.x, A10); A11 = ffma2(d11, wv1.y, A11);
            }
            __syncthreads();
            float* red = Asc;             // 8 x 512 partials
            {
                float r0, r1, r2, r3;
                upk2(A00, r0, r1); upk2(A01, r2, r3);
                *(float4*)&red[ks * 512 + b0 * 16 + ciq * 4] =
                    make_float4(r0, r1, r2, r3);
                upk2(A10, r0, r1); upk2(A11, r2, r3);
                *(float4*)&red[ks * 512 + b1 * 16 + ciq * 4] =
                    make_float4(r0, r1, r2, r3);
            }
            __syncthreads();
            {
                float g = xkv;
                #pragma unroll
                for (int s2 = 0; s2 < 8; s2++) g += red[s2 * 512 + tid];
                gate_s[tid] = g;
            }
            __syncthreads();
            if (tid < 128) {
                int b = tid >> 2, jj = tid & 3;
                float gi = hsig(gate_s[b * 16 + 0  + jj]);
                float gf = hsig(gate_s[b * 16 + 4  + jj]);
                float gg = my_tanh(gate_s[b * 16 + 8  + jj]);
                float go = hsig(gate_s[b * 16 + 12 + jj]);
                float cn = gf * c_s[tid] + gi * gg;
                c_s[tid] = cn;
                float hn = go * my_tanh(cn);
                int idx = b * UU + u0 + jj;
                g_hbuf[idx] = hn;
                out[((size_t)b * TT + t) * UU + u0 + jj] = hn;
            }
        }
        bar_sync(&g_gcnt, &g_ggen, NCTA);
    }
}

// ---------------------------------------------------------------------------
extern "C" void kernel_launch(void* const* d_in, const int* in_sizes, int n_in,
                              void* d_out, int out_size) {
    const float* x    = (const float*)d_in[0];
    const float* Wk   = (const float*)d_in[1];  // kernel (D,4U)
    const float* R    = (const float*)d_in[2];  // recurrent_kernel (U,4U)
    const float* A    = (const float*)d_in[3];  // attention_kernel (D,4U)
    const float* Wa   = (const float*)d_in[4];  // attention_W (D,U)
    const float* Ua   = (const float*)d_in[5];  // attention_U (U,U)
    const float* V    = (const float*)d_in[6];  // attention_V (U,1)
    const float* bias = (const float*)d_in[7];  // (4U)
    const float* ab   = (const float*)d_in[8];  // attention_b (U)
    float* out = (float*)d_out;

    const int SCAN_SMEM = 54912 * 4;  // 219648 B
    cudaFuncSetAttribute(k_scan, cudaFuncAttributeMaxDynamicSharedMemorySize,
                         SCAN_SMEM);

    k_pre<<<dim3(40, 32), 256>>>(x, Wk, Wa, bias, ab);
    k_scan<<<NCTA, NTHR, SCAN_SMEM>>>(x, R, A, Ua, V, out);
}